// round 11
// baseline (speedup 1.0000x reference)
#include <cuda_runtime.h>
#include <cstddef>

#define NR 8192                      // N nodes
#define STAT_BINS 64
static const long long NN = (long long)NR * NR;

// ---------------- device scratch (no allocations allowed) ----------------
__device__ double g_stats[6 * 2 * STAT_BINS];     // [slot][sum|sumsq][bin]
__device__ __align__(16) float g_z1[NR * 4];
__device__ __align__(16) float g_z2[NR * 4];
__device__ __align__(16) float g_r1[NR * 4];
__device__ __align__(16) float g_r2[NR * 4];

struct MV {
    const float* A;   // [N,N]
    const float* b;   // bias (dout floats, dout<=4)
    int zsel;         // 0 -> g_z1, 1 -> g_z2   (input z)
    int rsel;         // 0 -> g_r1, 1 -> g_r2   (output relu(A@z+b))
    int slot;         // BN stats slot
};

__device__ __forceinline__ float* zbuf(int s) { return s ? g_z2 : g_z1; }
__device__ __forceinline__ float* rbuf(int s) { return s ? g_r2 : g_r1; }

// ---------------- init: zero stats, z1 = F1*w11, z2 = F2*w21 -------------
__global__ void k_init(const float* __restrict__ x,
                       const float* __restrict__ w11,
                       const float* __restrict__ w21) {
    int i = blockIdx.x * blockDim.x + threadIdx.x;
    if (i < 6 * 2 * STAT_BINS) g_stats[i] = 0.0;
    if (i < NR) {
        float f1 = x[i];
        float f2 = x[NR + i];
#pragma unroll
        for (int j = 0; j < 4; j++) {
            g_z1[i * 4 + j] = f1 * w11[j];
            g_z2[i * 4 + j] = f2 * w21[j];
        }
    }
}

// ---------------- big matvec, dout = 4 -----------------------------------
// out[r][j] = relu( sum_c A[r][c] * z[c][j] + b[j] ), stats accumulated.
__global__ void __launch_bounds__(256) k_matvec4(MV m0, MV m1, int bpm) {
    int mat = (blockIdx.x >= bpm) ? 1 : 0;
    MV m = mat ? m1 : m0;
    int row0 = (blockIdx.x - mat * bpm) * 8;
    int tid = threadIdx.x;

    const float4* __restrict__ A4 = (const float4*)m.A;
    const float4* __restrict__ z4 = (const float4*)zbuf(m.zsel);

    float acc[8][4];
#pragma unroll
    for (int r = 0; r < 8; r++)
#pragma unroll
        for (int j = 0; j < 4; j++) acc[r][j] = 0.f;

#pragma unroll 2
    for (int it = 0; it < 8; it++) {
        int cg = it * 256 + tid;                   // 4-column group
        float4 za = z4[cg * 4 + 0];
        float4 zb = z4[cg * 4 + 1];
        float4 zc = z4[cg * 4 + 2];
        float4 zd = z4[cg * 4 + 3];
#pragma unroll
        for (int r = 0; r < 8; r++) {
            float4 av = A4[(size_t)(row0 + r) * 2048 + cg];
            acc[r][0] += av.x * za.x + av.y * zb.x + av.z * zc.x + av.w * zd.x;
            acc[r][1] += av.x * za.y + av.y * zb.y + av.z * zc.y + av.w * zd.y;
            acc[r][2] += av.x * za.z + av.y * zb.z + av.z * zc.z + av.w * zd.z;
            acc[r][3] += av.x * za.w + av.y * zb.w + av.z * zc.w + av.w * zd.w;
        }
    }

    __shared__ float sred[8][32];
    int lane = tid & 31, warp = tid >> 5;
#pragma unroll
    for (int v = 0; v < 32; v++) {
        float val = acc[v >> 2][v & 3];
#pragma unroll
        for (int off = 16; off; off >>= 1)
            val += __shfl_xor_sync(0xffffffffu, val, off);
        if (lane == v) sred[warp][v] = val;
    }
    __syncthreads();
    if (warp == 0) {
        float h = 0.f;
#pragma unroll
        for (int w = 0; w < 8; w++) h += sred[w][lane];
        h += m.b[lane & 3];
        float rv = fmaxf(h, 0.f);
        rbuf(m.rsel)[(size_t)(row0 + (lane >> 2)) * 4 + (lane & 3)] = rv;

        float s = rv, q = rv * rv;
#pragma unroll
        for (int off = 16; off; off >>= 1) {
            s += __shfl_xor_sync(0xffffffffu, s, off);
            q += __shfl_xor_sync(0xffffffffu, q, off);
        }
        if (lane == 0) {
            int bin = blockIdx.x & (STAT_BINS - 1);
            atomicAdd(&g_stats[(2 * m.slot) * STAT_BINS + bin], (double)s);
            atomicAdd(&g_stats[(2 * m.slot + 1) * STAT_BINS + bin], (double)q);
        }
    }
}

// ---------------- big matvec, dout = 1 -----------------------------------
__global__ void __launch_bounds__(256) k_matvec1(MV m0, MV m1, int bpm) {
    int mat = (blockIdx.x >= bpm) ? 1 : 0;
    MV m = mat ? m1 : m0;
    int row0 = (blockIdx.x - mat * bpm) * 8;
    int tid = threadIdx.x;

    const float4* __restrict__ A4 = (const float4*)m.A;
    const float4* __restrict__ z4 = (const float4*)zbuf(m.zsel);

    float acc[8];
#pragma unroll
    for (int r = 0; r < 8; r++) acc[r] = 0.f;

#pragma unroll 2
    for (int it = 0; it < 8; it++) {
        int cg = it * 256 + tid;
        float4 zv = z4[cg];
#pragma unroll
        for (int r = 0; r < 8; r++) {
            float4 av = A4[(size_t)(row0 + r) * 2048 + cg];
            acc[r] += av.x * zv.x + av.y * zv.y + av.z * zv.z + av.w * zv.w;
        }
    }

    __shared__ float sred[8][8];
    int lane = tid & 31, warp = tid >> 5;
#pragma unroll
    for (int v = 0; v < 8; v++) {
        float val = acc[v];
#pragma unroll
        for (int off = 16; off; off >>= 1)
            val += __shfl_xor_sync(0xffffffffu, val, off);
        if (lane == v) sred[warp][v] = val;
    }
    __syncthreads();
    if (warp == 0) {
        float rv = 0.f;
        if (lane < 8) {
            float h = 0.f;
#pragma unroll
            for (int w = 0; w < 8; w++) h += sred[w][lane];
            h += m.b[0];
            rv = fmaxf(h, 0.f);
            rbuf(m.rsel)[row0 + lane] = rv;
        }
        float s = rv, q = rv * rv;
#pragma unroll
        for (int off = 16; off; off >>= 1) {
            s += __shfl_xor_sync(0xffffffffu, s, off);
            q += __shfl_xor_sync(0xffffffffu, q, off);
        }
        if (lane == 0) {
            int bin = blockIdx.x & (STAT_BINS - 1);
            atomicAdd(&g_stats[(2 * m.slot) * STAT_BINS + bin], (double)s);
            atomicAdd(&g_stats[(2 * m.slot + 1) * STAT_BINS + bin], (double)q);
        }
    }
}

// ---------------- BN param finalize --------------------------------------
__device__ __forceinline__ void bn_params(int slot, float Mcount, float gamma,
                                          float beta, float& sc, float& sh) {
    double s = 0.0, q = 0.0;
#pragma unroll 4
    for (int b = 0; b < STAT_BINS; b++) {
        s += g_stats[(2 * slot) * STAT_BINS + b];
        q += g_stats[(2 * slot + 1) * STAT_BINS + b];
    }
    double mean = s / (double)Mcount;
    double var = q / (double)Mcount - mean * mean;
    sc = gamma * rsqrtf((float)var + 1e-5f);
    sh = beta - sc * (float)mean;  // out = sc*x + sh
}

// stage 1 -> 2: BN(slot0/1, M=4N), no post-relu, fold @w12/@w22 -> z [N,1]
__global__ void k_norm_s1(const float* __restrict__ w12,
                          const float* __restrict__ w22,
                          const float* __restrict__ g,
                          const float* __restrict__ be) {
    __shared__ float ssc[2], ssh[2];
    if (threadIdx.x == 0) bn_params(0, 4.f * NR, *g, *be, ssc[0], ssh[0]);
    if (threadIdx.x == 1) bn_params(1, 4.f * NR, *g, *be, ssc[1], ssh[1]);
    __syncthreads();
    int i = blockIdx.x * blockDim.x + threadIdx.x;
    if (i < NR) {
        float z1 = 0.f, z2 = 0.f;
#pragma unroll
        for (int j = 0; j < 4; j++) {
            z1 += (ssc[0] * g_r1[i * 4 + j] + ssh[0]) * w12[j];
            z2 += (ssc[1] * g_r2[i * 4 + j] + ssh[1]) * w22[j];
        }
        g_z1[i] = z1;
        g_z2[i] = z2;
    }
}

// stage 2 -> concat -> stage c1: BN(slot2/3, M=N) + post-relu, fold @wc1
__global__ void k_norm_s2(const float* __restrict__ wc1,
                          const float* __restrict__ g,
                          const float* __restrict__ be) {
    __shared__ float ssc[2], ssh[2];
    if (threadIdx.x == 0) bn_params(2, (float)NR, *g, *be, ssc[0], ssh[0]);
    if (threadIdx.x == 1) bn_params(3, (float)NR, *g, *be, ssc[1], ssh[1]);
    __syncthreads();
    int i = blockIdx.x * blockDim.x + threadIdx.x;
    if (i < NR) {
        float f1 = fmaxf(ssc[0] * g_r1[i] + ssh[0], 0.f);
        float f2 = fmaxf(ssc[1] * g_r2[i] + ssh[1], 0.f);
#pragma unroll
        for (int j = 0; j < 4; j++)
            g_z1[i * 4 + j] = f1 * wc1[j] + f2 * wc1[4 + j];
    }
}

// stage c1 -> c2: BN(slot4, M=4N), no post-relu, fold @wc2 -> z [N,1]
__global__ void k_norm_s3(const float* __restrict__ wc2,
                          const float* __restrict__ g,
                          const float* __restrict__ be) {
    __shared__ float ssc, ssh;
    if (threadIdx.x == 0) bn_params(4, 4.f * NR, *g, *be, ssc, ssh);
    __syncthreads();
    int i = blockIdx.x * blockDim.x + threadIdx.x;
    if (i < NR) {
        float z = 0.f;
#pragma unroll
        for (int j = 0; j < 4; j++)
            z += (ssc * g_r1[i * 4 + j] + ssh) * wc2[j];
        g_z2[i] = z;
    }
}

// final: BN(slot5, M=N) + post-relu -> out
__global__ void k_out(const float* __restrict__ g,
                      const float* __restrict__ be,
                      float* __restrict__ out) {
    __shared__ float ssc, ssh;
    if (threadIdx.x == 0) bn_params(5, (float)NR, *g, *be, ssc, ssh);
    __syncthreads();
    int i = blockIdx.x * blockDim.x + threadIdx.x;
    if (i < NR) out[i] = fmaxf(ssc * g_r2[i] + ssh, 0.f);
}

// ---------------- host ----------------------------------------------------
extern "C" void kernel_launch(void* const* d_in, const int* in_sizes, int n_in,
                              void* d_out, int out_size) {
    const float* x     = (const float*)d_in[0];
    const float* adj   = (const float*)d_in[1];
    const float* w11   = (const float*)d_in[2];
    const float* b11   = (const float*)d_in[3];
    const float* w12   = (const float*)d_in[4];
    const float* b12   = (const float*)d_in[5];
    const float* w21   = (const float*)d_in[6];
    const float* b21   = (const float*)d_in[7];
    const float* w22   = (const float*)d_in[8];
    const float* b22   = (const float*)d_in[9];
    const float* wc1   = (const float*)d_in[10];
    const float* bc1   = (const float*)d_in[11];
    const float* wc2   = (const float*)d_in[12];
    const float* bc2   = (const float*)d_in[13];
    const float* gamma = (const float*)d_in[14];
    const float* beta  = (const float*)d_in[15];

    const float* A1  = adj;
    const float* A2  = adj + NN;
    const float* A12 = adj + 2 * NN;
    float* out = (float*)d_out;

    const int bpm = NR / 8;  // 1024 blocks per matrix

    // z1 = F1@w11, z2 = F2@w21 ; zero stats
    k_init<<<NR / 256, 256>>>(x, w11, w21);

    // block 1 (A1) + block 3 (A2), dout=4
    MV m0 = {A1, b11, 0, 0, 0};
    MV m1 = {A2, b21, 1, 1, 1};
    k_matvec4<<<2 * bpm, 256>>>(m0, m1, bpm);

    // BN + fold @w12/@w22
    k_norm_s1<<<NR / 256, 256>>>(w12, w22, gamma, beta);

    // block 2 (A1) + block 4 (A2), dout=1
    MV m2 = {A1, b12, 0, 0, 2};
    MV m3 = {A2, b22, 1, 1, 3};
    k_matvec1<<<2 * bpm, 256>>>(m2, m3, bpm);

    // BN + post-relu + concat + fold @wc1
    k_norm_s2<<<NR / 256, 256>>>(wc1, gamma, beta);

    // block c1 (A12), dout=4
    MV m4 = {A12, bc1, 0, 0, 4};
    k_matvec4<<<bpm, 256>>>(m4, m4, bpm);

    // BN + fold @wc2
    k_norm_s3<<<NR / 256, 256>>>(wc2, gamma, beta);

    // block c2 (A12), dout=1
    MV m5 = {A12, bc2, 1, 1, 5};
    k_matvec1<<<bpm, 256>>>(m5, m5, bpm);

    // final BN + relu -> out
    k_out<<<NR / 256, 256>>>(gamma, beta, out);
}